// round 1
// baseline (speedup 1.0000x reference)
#include <cuda_runtime.h>
#include <math.h>

// ---------------------------------------------------------------------------
// Problem constants
// ---------------------------------------------------------------------------
#define NB     4096
#define K5     5
// conv1: 1 -> 32 channels, 28x28, pad 2, pool -> 14x14
// conv2: 32 -> 64 channels, 14x14, pad 2, pool -> 7x7
// fc1:   3136 -> 128, relu
// fc2:   128 -> 10

// ---------------------------------------------------------------------------
// Device scratch (static __device__ arrays — no runtime allocation)
// ---------------------------------------------------------------------------
__device__ float g_K1[32 * 25];                 // [co][ky*5+kx]
__device__ float g_K2[32 * 64 * 25];            // [ci][co][ky*5+kx]
__device__ float g_pool1[NB * 32 * 14 * 14];    // conv1 output after relu+pool
__device__ float g_pool2[NB * 64 * 7 * 7];      // conv2 output after relu+pool
__device__ float g_fc1o[NB * 128];              // fc1 output after relu
__device__ float g_fc1wt[3136 * 128];           // fc1_w transposed: [k][n]

// ---------------------------------------------------------------------------
// Kernel 1: build dense DCLS kernels from (w, p) via bilinear scatter
// ---------------------------------------------------------------------------
__global__ void build_kernels_k(const float* __restrict__ w1,
                                const float* __restrict__ p1,
                                const float* __restrict__ w2,
                                const float* __restrict__ p2) {
    int t = blockIdx.x * blockDim.x + threadIdx.x;
    if (t >= 32 + 64 * 32) return;

    float acc[36];
#pragma unroll
    for (int i = 0; i < 36; i++) acc[i] = 0.f;

    if (t < 32) {
        // conv1 kernel: co = t, ci = 0, Kc = 16
        int co = t;
        for (int kc = 0; kc < 16; kc++) {
            float wv = w1[co * 16 + kc];
            float pa = p1[0 * 32 * 16 + co * 16 + kc];
            float pb = p1[1 * 32 * 16 + co * 16 + kc];
            pa = fminf(fmaxf(pa, -2.f), 2.f) + 2.f;
            pb = fminf(fmaxf(pb, -2.f), 2.f) + 2.f;
            int   i1 = (int)floorf(pa), i2 = (int)floorf(pb);
            float r1 = pa - (float)i1,  r2 = pb - (float)i2;
            acc[i1 * 6 + i2]           += wv * (1.f - r1) * (1.f - r2);
            acc[(i1 + 1) * 6 + i2]     += wv * r1 * (1.f - r2);
            acc[i1 * 6 + i2 + 1]       += wv * (1.f - r1) * r2;
            acc[(i1 + 1) * 6 + i2 + 1] += wv * r1 * r2;
        }
        for (int ky = 0; ky < 5; ky++)
            for (int kx = 0; kx < 5; kx++)
                g_K1[co * 25 + ky * 5 + kx] = acc[ky * 6 + kx];
    } else {
        // conv2 kernel: idx over (co, ci), Kc = 32
        int idx = t - 32;
        int co = idx / 32, ci = idx % 32;
        for (int kc = 0; kc < 32; kc++) {
            float wv = w2[(co * 32 + ci) * 32 + kc];
            float pa = p2[0 * 64 * 32 * 32 + (co * 32 + ci) * 32 + kc];
            float pb = p2[1 * 64 * 32 * 32 + (co * 32 + ci) * 32 + kc];
            pa = fminf(fmaxf(pa, -2.f), 2.f) + 2.f;
            pb = fminf(fmaxf(pb, -2.f), 2.f) + 2.f;
            int   i1 = (int)floorf(pa), i2 = (int)floorf(pb);
            float r1 = pa - (float)i1,  r2 = pb - (float)i2;
            acc[i1 * 6 + i2]           += wv * (1.f - r1) * (1.f - r2);
            acc[(i1 + 1) * 6 + i2]     += wv * r1 * (1.f - r2);
            acc[i1 * 6 + i2 + 1]       += wv * (1.f - r1) * r2;
            acc[(i1 + 1) * 6 + i2 + 1] += wv * r1 * r2;
        }
        // store as [ci][co][q] so conv2's smem chunk copy is a straight memcpy
        for (int ky = 0; ky < 5; ky++)
            for (int kx = 0; kx < 5; kx++)
                g_K2[(ci * 64 + co) * 25 + ky * 5 + kx] = acc[ky * 6 + kx];
    }
}

// ---------------------------------------------------------------------------
// Kernel 2: transpose fc1_w (128 x 3136) -> g_fc1wt (3136 x 128)
// ---------------------------------------------------------------------------
__global__ void transpose_fc1w_k(const float* __restrict__ w) {
    int idx = blockIdx.x * blockDim.x + threadIdx.x;
    if (idx < 3136 * 128) {
        int k = idx / 128, n = idx % 128;
        g_fc1wt[idx] = w[n * 3136 + k];
    }
}

// ---------------------------------------------------------------------------
// Kernel 3: conv1 (1->32, pad 2) + bias + relu + 2x2 maxpool, fused.
// One block per image. Image and all 32 kernels live in smem.
// ---------------------------------------------------------------------------
__global__ __launch_bounds__(256) void conv1_k(const float* __restrict__ x,
                                               const float* __restrict__ b1) {
    __shared__ float xs[784];    // 28x28
    __shared__ float ks[800];    // 32 x 25
    int b = blockIdx.x;
    const float* xp = x + b * 784;
    for (int i = threadIdx.x; i < 784; i += 256) xs[i] = xp[i];
    for (int i = threadIdx.x; i < 800; i += 256) ks[i] = g_K1[i];
    __syncthreads();

    for (int o = threadIdx.x; o < 32 * 196; o += 256) {
        int co = o / 196, rem = o % 196;
        int yp = rem / 14, xq = rem % 14;
        int y0 = 2 * yp - 2, x0 = 2 * xq - 2;

        float patch[36];
#pragma unroll
        for (int dy = 0; dy < 6; dy++) {
            int yy = y0 + dy;
            bool yok = (yy >= 0) && (yy < 28);
#pragma unroll
            for (int dx = 0; dx < 6; dx++) {
                int xx = x0 + dx;
                patch[dy * 6 + dx] = (yok && xx >= 0 && xx < 28) ? xs[yy * 28 + xx] : 0.f;
            }
        }
        const float* kk = &ks[co * 25];
        float v0 = 0.f, v1 = 0.f, v2 = 0.f, v3 = 0.f;
#pragma unroll
        for (int ky = 0; ky < 5; ky++) {
#pragma unroll
            for (int kx = 0; kx < 5; kx++) {
                float wv = kk[ky * 5 + kx];
                v0 += wv * patch[(ky)     * 6 + kx];
                v1 += wv * patch[(ky)     * 6 + kx + 1];
                v2 += wv * patch[(ky + 1) * 6 + kx];
                v3 += wv * patch[(ky + 1) * 6 + kx + 1];
            }
        }
        float m = fmaxf(fmaxf(v0, v1), fmaxf(v2, v3)) + b1[co];
        g_pool1[(b * 32 + co) * 196 + yp * 14 + xq] = fmaxf(m, 0.f);
    }
}

// ---------------------------------------------------------------------------
// Kernel 4: conv2 (32->64, pad 2) + bias + relu + 2x2 maxpool, fused.
// One block per image, 448 threads = (yp in 0..6) x (co in 0..63).
// Each thread computes two full 14-wide conv rows (28 accumulators) with a
// rolling 2x18-register input row window -> 700 FMA per ci vs ~110 LDS.
// Weights staged in smem in two 16-ci chunks ([ci][co][25] layout: the
// per-lane co-stride of 25 is coprime with 32 banks -> conflict-free).
// ---------------------------------------------------------------------------
#define C2_THREADS 448
#define C2_SMEM_FLOATS (6272 + 16 * 64 * 25)   // input + one weight chunk

__global__ __launch_bounds__(C2_THREADS, 1) void conv2_k(const float* __restrict__ b2) {
    extern __shared__ float sm[];
    float* in_s = sm;            // 32 x 14 x 14 = 6272
    float* ws   = sm + 6272;     // 16 x 64 x 25 = 25600

    int b = blockIdx.x;
    int t = threadIdx.x;
    const float* ip = g_pool1 + b * 6272;
    for (int i = t; i < 6272; i += C2_THREADS) in_s[i] = ip[i];

    int yp = t / 64;     // 0..6
    int co = t % 64;     // 0..63
    int rbase = 2 * yp - 2;

    float acc0[14], acc1[14];
#pragma unroll
    for (int i = 0; i < 14; i++) { acc0[i] = 0.f; acc1[i] = 0.f; }

    for (int chunk = 0; chunk < 2; chunk++) {
        __syncthreads();  // covers initial in_s load and prior chunk's reads
        const float* wsrc = g_K2 + chunk * 25600;
        for (int i = t; i < 25600; i += C2_THREADS) ws[i] = wsrc[i];
        __syncthreads();

        for (int cil = 0; cil < 16; cil++) {
            int ci = chunk * 16 + cil;
            const float* inc = in_s + ci * 196;
            const float* wp  = ws + (cil * 64 + co) * 25;

            float rowA[18], rowB[18];
            // rowA = input row rbase (cols -2..15, zero-padded)
            {
                int rr = rbase;
                bool rok = (rr >= 0) && (rr < 14);
#pragma unroll
                for (int j = 0; j < 18; j++) {
                    int cc = j - 2;
                    rowA[j] = (rok && cc >= 0 && cc < 14) ? inc[rr * 14 + cc] : 0.f;
                }
            }
#pragma unroll
            for (int ky = 0; ky < 5; ky++) {
                int rr = rbase + ky + 1;
                bool rok = (rr >= 0) && (rr < 14);
#pragma unroll
                for (int j = 0; j < 18; j++) {
                    int cc = j - 2;
                    rowB[j] = (rok && cc >= 0 && cc < 14) ? inc[rr * 14 + cc] : 0.f;
                }
#pragma unroll
                for (int kx = 0; kx < 5; kx++) {
                    float wv = wp[ky * 5 + kx];
#pragma unroll
                    for (int xx = 0; xx < 14; xx++) {
                        acc0[xx] += wv * rowA[xx + kx];   // conv row 2*yp
                        acc1[xx] += wv * rowB[xx + kx];   // conv row 2*yp+1
                    }
                }
#pragma unroll
                for (int j = 0; j < 18; j++) rowA[j] = rowB[j];
            }
        }
    }

    float bias = b2[co];
    float* op = g_pool2 + (b * 64 + co) * 49 + yp * 7;
#pragma unroll
    for (int xp = 0; xp < 7; xp++) {
        float m = fmaxf(fmaxf(acc0[2 * xp], acc0[2 * xp + 1]),
                        fmaxf(acc1[2 * xp], acc1[2 * xp + 1]));
        op[xp] = fmaxf(m + bias, 0.f);
    }
}

// ---------------------------------------------------------------------------
// Kernel 5: fc1 GEMM  C[4096,128] = pool2_flat[4096,3136] @ Wt[3136,128]
//           + bias, relu.  Tiles: BM=32, BN=128, BK=32. 256 thr, micro 4x4.
// ---------------------------------------------------------------------------
__global__ __launch_bounds__(256) void fc1_k(const float* __restrict__ fc1_b) {
    __shared__ float As[32 * 32];    // [mm][kk]
    __shared__ float Bs[32 * 128];   // [kk][n]

    int m0 = blockIdx.x * 32;
    int tid = threadIdx.x;
    int tm = tid / 32;   // 0..7  -> m = m0 + tm*4 + j
    int tn = tid % 32;   // 0..31 -> n = tn*4 + jj

    float c[4][4];
#pragma unroll
    for (int i = 0; i < 4; i++)
#pragma unroll
        for (int j = 0; j < 4; j++) c[i][j] = 0.f;

    const float* A = g_pool2;  // flat [4096][3136]

    for (int k0 = 0; k0 < 3136; k0 += 32) {
        // load A tile: 32x32, coalesced over k
#pragma unroll
        for (int l = 0; l < 4; l++) {
            int i = tid + l * 256;
            int mm = i / 32, kk = i % 32;
            As[mm * 32 + kk] = A[(m0 + mm) * 3136 + k0 + kk];
        }
        // load B tile: 32x128 from pre-transposed Wt[k][n], coalesced over n
#pragma unroll
        for (int l = 0; l < 16; l++) {
            int i = tid + l * 256;
            int kk = i / 128, n = i % 128;
            Bs[kk * 128 + n] = g_fc1wt[(k0 + kk) * 128 + n];
        }
        __syncthreads();

#pragma unroll
        for (int kk = 0; kk < 32; kk++) {
            float a0 = As[(tm * 4 + 0) * 32 + kk];
            float a1 = As[(tm * 4 + 1) * 32 + kk];
            float a2 = As[(tm * 4 + 2) * 32 + kk];
            float a3 = As[(tm * 4 + 3) * 32 + kk];
            float4 bv = *(const float4*)&Bs[kk * 128 + tn * 4];
            c[0][0] += a0 * bv.x; c[0][1] += a0 * bv.y; c[0][2] += a0 * bv.z; c[0][3] += a0 * bv.w;
            c[1][0] += a1 * bv.x; c[1][1] += a1 * bv.y; c[1][2] += a1 * bv.z; c[1][3] += a1 * bv.w;
            c[2][0] += a2 * bv.x; c[2][1] += a2 * bv.y; c[2][2] += a2 * bv.z; c[2][3] += a2 * bv.w;
            c[3][0] += a3 * bv.x; c[3][1] += a3 * bv.y; c[3][2] += a3 * bv.z; c[3][3] += a3 * bv.w;
        }
        __syncthreads();
    }

#pragma unroll
    for (int j = 0; j < 4; j++) {
        int m = m0 + tm * 4 + j;
#pragma unroll
        for (int jj = 0; jj < 4; jj++) {
            int n = tn * 4 + jj;
            g_fc1o[m * 128 + n] = fmaxf(c[j][jj] + fc1_b[n], 0.f);
        }
    }
}

// ---------------------------------------------------------------------------
// Kernel 6: fc2  out[4096,10] = fc1o[4096,128] @ fc2_w[10,128]^T + b
// ---------------------------------------------------------------------------
__global__ __launch_bounds__(256) void fc2_k(const float* __restrict__ fc2_w,
                                             const float* __restrict__ fc2_b,
                                             float* __restrict__ out) {
    int idx = blockIdx.x * blockDim.x + threadIdx.x;
    if (idx >= NB * 10) return;
    int m = idx / 10, n = idx % 10;
    const float4* h = (const float4*)(g_fc1o + m * 128);
    const float4* w = (const float4*)(fc2_w + n * 128);
    float s = 0.f;
#pragma unroll
    for (int i = 0; i < 32; i++) {
        float4 a = h[i], bb = w[i];
        s += a.x * bb.x + a.y * bb.y + a.z * bb.z + a.w * bb.w;
    }
    out[idx] = s + fc2_b[n];
}

// ---------------------------------------------------------------------------
// Launch
// ---------------------------------------------------------------------------
extern "C" void kernel_launch(void* const* d_in, const int* in_sizes, int n_in,
                              void* d_out, int out_size) {
    const float* x     = (const float*)d_in[0];
    const float* w1    = (const float*)d_in[1];
    const float* p1    = (const float*)d_in[2];
    const float* b1    = (const float*)d_in[3];
    const float* w2    = (const float*)d_in[4];
    const float* p2    = (const float*)d_in[5];
    const float* b2    = (const float*)d_in[6];
    const float* fc1w  = (const float*)d_in[7];
    const float* fc1b  = (const float*)d_in[8];
    const float* fc2w  = (const float*)d_in[9];
    const float* fc2b  = (const float*)d_in[10];
    float* out = (float*)d_out;

    static_assert(C2_SMEM_FLOATS * 4 == 127488, "smem size");
    cudaFuncSetAttribute(conv2_k, cudaFuncAttributeMaxDynamicSharedMemorySize,
                         C2_SMEM_FLOATS * 4);

    build_kernels_k<<<(32 + 64 * 32 + 127) / 128, 128>>>(w1, p1, w2, p2);
    transpose_fc1w_k<<<(3136 * 128 + 255) / 256, 256>>>(fc1w);
    conv1_k<<<NB, 256>>>(x, b1);
    conv2_k<<<NB, C2_THREADS, C2_SMEM_FLOATS * 4>>>(b2);
    fc1_k<<<NB / 32, 256>>>(fc1b);
    fc2_k<<<(NB * 10 + 255) / 256, 256>>>(fc2w, fc2b, out);
}

// round 3
// speedup vs baseline: 1.1821x; 1.1821x over previous
#include <cuda_runtime.h>
#include <math.h>

// ---------------------------------------------------------------------------
// Problem constants
// ---------------------------------------------------------------------------
#define NB     4096
// conv1: 1 -> 32 channels, 28x28, pad 2, pool -> 14x14 (written zero-padded 18x18)
// conv2: 32 -> 64 channels, 14x14, pad 2, pool -> 7x7
// fc1:   3136 -> 128, relu
// fc2:   128 -> 10

// Padded conv1-output geometry: rows/cols -2..15 -> 18x18 = 324 cells per ci
#define P1R 18
#define P1C 18
#define P1A (P1R * P1C)          // 324

// ---------------------------------------------------------------------------
// Device scratch (static __device__ arrays — no runtime allocation)
// ---------------------------------------------------------------------------
__device__ float g_K1[32 * 25];                  // [co][ky*5+kx]
__device__ float g_K2[32 * 64 * 25];             // [ci][co][ky*5+kx]
__device__ float g_pool1[NB * 32 * P1A];         // conv1 out, relu+pool, ZERO-PADDED
__device__ float g_pool2[NB * 64 * 7 * 7];       // conv2 out, relu+pool
__device__ float g_fc1o[NB * 128];               // fc1 out, relu
__device__ float g_fc1wt[3136 * 128];            // fc1_w transposed: [k][n]

// ---------------------------------------------------------------------------
// Kernel 1: build dense DCLS kernels from (w, p) via bilinear scatter
// ---------------------------------------------------------------------------
__global__ void build_kernels_k(const float* __restrict__ w1,
                                const float* __restrict__ p1,
                                const float* __restrict__ w2,
                                const float* __restrict__ p2) {
    int t = blockIdx.x * blockDim.x + threadIdx.x;
    if (t >= 32 + 64 * 32) return;

    float acc[36];
#pragma unroll
    for (int i = 0; i < 36; i++) acc[i] = 0.f;

    if (t < 32) {
        int co = t;
        for (int kc = 0; kc < 16; kc++) {
            float wv = w1[co * 16 + kc];
            float pa = p1[0 * 32 * 16 + co * 16 + kc];
            float pb = p1[1 * 32 * 16 + co * 16 + kc];
            pa = fminf(fmaxf(pa, -2.f), 2.f) + 2.f;
            pb = fminf(fmaxf(pb, -2.f), 2.f) + 2.f;
            int   i1 = (int)floorf(pa), i2 = (int)floorf(pb);
            float r1 = pa - (float)i1,  r2 = pb - (float)i2;
            acc[i1 * 6 + i2]           += wv * (1.f - r1) * (1.f - r2);
            acc[(i1 + 1) * 6 + i2]     += wv * r1 * (1.f - r2);
            acc[i1 * 6 + i2 + 1]       += wv * (1.f - r1) * r2;
            acc[(i1 + 1) * 6 + i2 + 1] += wv * r1 * r2;
        }
        for (int ky = 0; ky < 5; ky++)
            for (int kx = 0; kx < 5; kx++)
                g_K1[co * 25 + ky * 5 + kx] = acc[ky * 6 + kx];
    } else {
        int idx = t - 32;
        int co = idx / 32, ci = idx % 32;
        for (int kc = 0; kc < 32; kc++) {
            float wv = w2[(co * 32 + ci) * 32 + kc];
            float pa = p2[0 * 64 * 32 * 32 + (co * 32 + ci) * 32 + kc];
            float pb = p2[1 * 64 * 32 * 32 + (co * 32 + ci) * 32 + kc];
            pa = fminf(fmaxf(pa, -2.f), 2.f) + 2.f;
            pb = fminf(fmaxf(pb, -2.f), 2.f) + 2.f;
            int   i1 = (int)floorf(pa), i2 = (int)floorf(pb);
            float r1 = pa - (float)i1,  r2 = pb - (float)i2;
            acc[i1 * 6 + i2]           += wv * (1.f - r1) * (1.f - r2);
            acc[(i1 + 1) * 6 + i2]     += wv * r1 * (1.f - r2);
            acc[i1 * 6 + i2 + 1]       += wv * (1.f - r1) * r2;
            acc[(i1 + 1) * 6 + i2 + 1] += wv * r1 * r2;
        }
        // store as [ci][co][q] so conv2's smem chunk copy is a straight memcpy
        for (int ky = 0; ky < 5; ky++)
            for (int kx = 0; kx < 5; kx++)
                g_K2[(ci * 64 + co) * 25 + ky * 5 + kx] = acc[ky * 6 + kx];
    }
}

// ---------------------------------------------------------------------------
// Kernel 2: transpose fc1_w (128 x 3136) -> g_fc1wt (3136 x 128)
// ---------------------------------------------------------------------------
__global__ void transpose_fc1w_k(const float* __restrict__ w) {
    int idx = blockIdx.x * blockDim.x + threadIdx.x;
    if (idx < 3136 * 128) {
        int k = idx / 128, n = idx % 128;
        g_fc1wt[idx] = w[n * 3136 + k];
    }
}

// ---------------------------------------------------------------------------
// Kernel 3: conv1 (1->32, pad 2) + bias + relu + 2x2 maxpool, fused.
// One block per image. Image padded to 32x32 in smem (no predicates in the
// inner loops). Output written in ZERO-PADDED 18x18 layout for conv2.
// ---------------------------------------------------------------------------
__global__ __launch_bounds__(256) void conv1_k(const float* __restrict__ x,
                                               const float* __restrict__ b1) {
    __shared__ float xs[32 * 32];   // rows/cols -2..29
    __shared__ float ks[800];       // 32 x 25
    int b = blockIdx.x;
    const float* xp = x + b * 784;
    for (int i = threadIdx.x; i < 1024; i += 256) {
        int r = i / 32 - 2, c = i % 32 - 2;
        xs[i] = (r >= 0 && r < 28 && c >= 0 && c < 28) ? xp[r * 28 + c] : 0.f;
    }
    for (int i = threadIdx.x; i < 800; i += 256) ks[i] = g_K1[i];
    __syncthreads();

    float* outp = g_pool1 + b * 32 * P1A;
    // one pass over the padded output grid: 32 ci x 324 cells
    for (int o = threadIdx.x; o < 32 * P1A; o += 256) {
        int co = o / P1A, m = o % P1A;
        int pr = m / P1C, pc = m % P1C;        // padded coords
        int yp = pr - 2,  xq = pc - 2;         // pooled coords
        float outv = 0.f;
        if (yp >= 0 && yp < 14 && xq >= 0 && xq < 14) {
            int y0 = 2 * yp, x0 = 2 * xq;      // top-left input of 2x2 pool cell
            // patch rows y0-2 .. y0+3, cols x0-2 .. x0+3 in padded xs
            float patch[36];
#pragma unroll
            for (int dy = 0; dy < 6; dy++)
#pragma unroll
                for (int dx = 0; dx < 6; dx++)
                    patch[dy * 6 + dx] = xs[(y0 + dy) * 32 + (x0 + dx)];
            const float* kk = &ks[co * 25];
            float v0 = 0.f, v1 = 0.f, v2 = 0.f, v3 = 0.f;
#pragma unroll
            for (int ky = 0; ky < 5; ky++) {
#pragma unroll
                for (int kx = 0; kx < 5; kx++) {
                    float wv = kk[ky * 5 + kx];
                    v0 += wv * patch[(ky)     * 6 + kx];
                    v1 += wv * patch[(ky)     * 6 + kx + 1];
                    v2 += wv * patch[(ky + 1) * 6 + kx];
                    v3 += wv * patch[(ky + 1) * 6 + kx + 1];
                }
            }
            float mx = fmaxf(fmaxf(v0, v1), fmaxf(v2, v3)) + b1[co];
            outv = fmaxf(mx, 0.f);
        }
        outp[o] = outv;
    }
}

// ---------------------------------------------------------------------------
// Kernel 4: conv2 (32->64, pad 2) + bias + relu + 2x2 maxpool, fused.
// One block per image, 448 threads = (yp in 0..6) x (co in 0..63).
// Input arrives pre-padded (18x18 per ci) -> all LDS unconditional.
// Input-row-stationary inner loop: each of 6 padded rows is loaded once
// (18 LDS) and feeds both conv rows (up to 140 FMA) -> no MOV copies,
// no predicates. Weights streamed in 8-ci chunks (51 KB) so total smem is
// 92.7 KB and 2 CTAs co-reside per SM (28 warps).
// ---------------------------------------------------------------------------
#define C2_THREADS 448
#define C2_IN_FLOATS (32 * P1A)                 // 10368
#define C2_WCHUNK_CI 8
#define C2_W_FLOATS (C2_WCHUNK_CI * 64 * 25)    // 12800
#define C2_SMEM_FLOATS (C2_IN_FLOATS + C2_W_FLOATS)

__global__ __launch_bounds__(C2_THREADS, 2) void conv2_k(const float* __restrict__ b2) {
    extern __shared__ float sm[];
    float* in_s = sm;                 // 32 x 324 padded input
    float* ws   = sm + C2_IN_FLOATS;  // 8 x 64 x 25 weight chunk

    int b = blockIdx.x;
    int t = threadIdx.x;
    const float* ip = g_pool1 + b * C2_IN_FLOATS;
    for (int i = t; i < C2_IN_FLOATS; i += C2_THREADS) in_s[i] = ip[i];

    int yp = t / 64;     // 0..6
    int co = t % 64;     // 0..63
    int prow0 = 2 * yp;  // padded row index of first input row used

    float acc0[14], acc1[14];
#pragma unroll
    for (int i = 0; i < 14; i++) { acc0[i] = 0.f; acc1[i] = 0.f; }

    for (int chunk = 0; chunk < 4; chunk++) {
        __syncthreads();  // in_s ready / previous chunk consumed
        const float* wsrc = g_K2 + chunk * C2_W_FLOATS;
        for (int i = t; i < C2_W_FLOATS; i += C2_THREADS) ws[i] = wsrc[i];
        __syncthreads();

        for (int cil = 0; cil < C2_WCHUNK_CI; cil++) {
            int ci = chunk * C2_WCHUNK_CI + cil;
            const float* inc = in_s + ci * P1A;
            const float* wp  = ws + (cil * 64 + co) * 25;

#pragma unroll
            for (int j = 0; j < 6; j++) {
                float row[18];
                const float* rp = inc + (prow0 + j) * P1C;
#pragma unroll
                for (int c = 0; c < 18; c++) row[c] = rp[c];

                if (j < 5) {                 // contributes to conv row 2*yp, ky=j
#pragma unroll
                    for (int kx = 0; kx < 5; kx++) {
                        float wv = wp[j * 5 + kx];
#pragma unroll
                        for (int xx = 0; xx < 14; xx++)
                            acc0[xx] += wv * row[xx + kx];
                    }
                }
                if (j >= 1) {                // contributes to conv row 2*yp+1, ky=j-1
#pragma unroll
                    for (int kx = 0; kx < 5; kx++) {
                        float wv = wp[(j - 1) * 5 + kx];
#pragma unroll
                        for (int xx = 0; xx < 14; xx++)
                            acc1[xx] += wv * row[xx + kx];
                    }
                }
            }
        }
    }

    float bias = b2[co];
    float* op = g_pool2 + (b * 64 + co) * 49 + yp * 7;
#pragma unroll
    for (int xp = 0; xp < 7; xp++) {
        float m = fmaxf(fmaxf(acc0[2 * xp], acc0[2 * xp + 1]),
                        fmaxf(acc1[2 * xp], acc1[2 * xp + 1]));
        op[xp] = fmaxf(m + bias, 0.f);
    }
}

// ---------------------------------------------------------------------------
// Kernel 5: fc1 GEMM  C[4096,128] = pool2_flat[4096,3136] @ Wt[3136,128]
//           + bias, relu.  Tiles: BM=32, BN=128, BK=32. 256 thr, micro 4x4.
// ---------------------------------------------------------------------------
__global__ __launch_bounds__(256) void fc1_k(const float* __restrict__ fc1_b) {
    __shared__ float As[32 * 32];    // [mm][kk]
    __shared__ float Bs[32 * 128];   // [kk][n]

    int m0 = blockIdx.x * 32;
    int tid = threadIdx.x;
    int tm = tid / 32;
    int tn = tid % 32;

    float c[4][4];
#pragma unroll
    for (int i = 0; i < 4; i++)
#pragma unroll
        for (int j = 0; j < 4; j++) c[i][j] = 0.f;

    const float* A = g_pool2;

    for (int k0 = 0; k0 < 3136; k0 += 32) {
#pragma unroll
        for (int l = 0; l < 4; l++) {
            int i = tid + l * 256;
            int mm = i / 32, kk = i % 32;
            As[mm * 32 + kk] = A[(m0 + mm) * 3136 + k0 + kk];
        }
#pragma unroll
        for (int l = 0; l < 16; l++) {
            int i = tid + l * 256;
            int kk = i / 128, n = i % 128;
            Bs[kk * 128 + n] = g_fc1wt[(k0 + kk) * 128 + n];
        }
        __syncthreads();

#pragma unroll
        for (int kk = 0; kk < 32; kk++) {
            float a0 = As[(tm * 4 + 0) * 32 + kk];
            float a1 = As[(tm * 4 + 1) * 32 + kk];
            float a2 = As[(tm * 4 + 2) * 32 + kk];
            float a3 = As[(tm * 4 + 3) * 32 + kk];
            float4 bv = *(const float4*)&Bs[kk * 128 + tn * 4];
            c[0][0] += a0 * bv.x; c[0][1] += a0 * bv.y; c[0][2] += a0 * bv.z; c[0][3] += a0 * bv.w;
            c[1][0] += a1 * bv.x; c[1][1] += a1 * bv.y; c[1][2] += a1 * bv.z; c[1][3] += a1 * bv.w;
            c[2][0] += a2 * bv.x; c[2][1] += a2 * bv.y; c[2][2] += a2 * bv.z; c[2][3] += a2 * bv.w;
            c[3][0] += a3 * bv.x; c[3][1] += a3 * bv.y; c[3][2] += a3 * bv.z; c[3][3] += a3 * bv.w;
        }
        __syncthreads();
    }

#pragma unroll
    for (int j = 0; j < 4; j++) {
        int m = m0 + tm * 4 + j;
#pragma unroll
        for (int jj = 0; jj < 4; jj++) {
            int n = tn * 4 + jj;
            g_fc1o[m * 128 + n] = fmaxf(c[j][jj] + fc1_b[n], 0.f);
        }
    }
}

// ---------------------------------------------------------------------------
// Kernel 6: fc2  out[4096,10] = fc1o[4096,128] @ fc2_w[10,128]^T + b
// ---------------------------------------------------------------------------
__global__ __launch_bounds__(256) void fc2_k(const float* __restrict__ fc2_w,
                                             const float* __restrict__ fc2_b,
                                             float* __restrict__ out) {
    int idx = blockIdx.x * blockDim.x + threadIdx.x;
    if (idx >= NB * 10) return;
    int m = idx / 10, n = idx % 10;
    const float4* h = (const float4*)(g_fc1o + m * 128);
    const float4* w = (const float4*)(fc2_w + n * 128);
    float s = 0.f;
#pragma unroll
    for (int i = 0; i < 32; i++) {
        float4 a = h[i], bb = w[i];
        s += a.x * bb.x + a.y * bb.y + a.z * bb.z + a.w * bb.w;
    }
    out[idx] = s + fc2_b[n];
}

// ---------------------------------------------------------------------------
// Launch
// ---------------------------------------------------------------------------
extern "C" void kernel_launch(void* const* d_in, const int* in_sizes, int n_in,
                              void* d_out, int out_size) {
    const float* x     = (const float*)d_in[0];
    const float* w1    = (const float*)d_in[1];
    const float* p1    = (const float*)d_in[2];
    const float* b1    = (const float*)d_in[3];
    const float* w2    = (const float*)d_in[4];
    const float* p2    = (const float*)d_in[5];
    const float* b2    = (const float*)d_in[6];
    const float* fc1w  = (const float*)d_in[7];
    const float* fc1b  = (const float*)d_in[8];
    const float* fc2w  = (const float*)d_in[9];
    const float* fc2b  = (const float*)d_in[10];
    float* out = (float*)d_out;

    cudaFuncSetAttribute(conv2_k, cudaFuncAttributeMaxDynamicSharedMemorySize,
                         C2_SMEM_FLOATS * 4);

    build_kernels_k<<<(32 + 64 * 32 + 127) / 128, 128>>>(w1, p1, w2, p2);
    transpose_fc1w_k<<<(3136 * 128 + 255) / 256, 256>>>(fc1w);
    conv1_k<<<NB, 256>>>(x, b1);
    conv2_k<<<NB, C2_THREADS, C2_SMEM_FLOATS * 4>>>(b2);
    fc1_k<<<NB / 32, 256>>>(fc1b);
    fc2_k<<<(NB * 10 + 255) / 256, 256>>>(fc2w, fc2b, out);
}